// round 1
// baseline (speedup 1.0000x reference)
#include <cuda_runtime.h>
#include <math_constants.h>

#define B_ 32
#define H_ 8
#define L_ 2048
#define E_ 64
#define ROWS 32
#define NTHREADS (ROWS * 32)

// AutoCorrelation:
//   corr[b,h,l,d] = sum_e q[b,h,l,(e+d)%64] * k[b,h,l,e]   (== irfft(fft(q)*conj(fft(k))))
//   top-4 of corr over d, softmax, V_out[e] = sum_i p_i * v[(e+d_i)%64]
//   outputs: V (B,H,L,E) then corr transposed to (B,E,H,L)
__global__ __launch_bounds__(NTHREADS, 1)
void ac_kernel(const float* __restrict__ Q, const float* __restrict__ Kk,
               const float* __restrict__ Vv, float* __restrict__ outV,
               float* __restrict__ outC)
{
    __shared__ __align__(16) float s_q[ROWS][128];   // duplicated q: no wrap in inner loop
    __shared__ __align__(16) float s_k[ROWS][64];
    __shared__ __align__(16) float s_v[ROWS][64];
    __shared__ float s_c[ROWS][65];                  // corr staging, padded (bank-conflict-free transpose)

    const int w     = threadIdx.x >> 5;
    const int lane  = threadIdx.x & 31;
    const int ltile = blockIdx.x;
    const int bh    = blockIdx.y;
    const int h     = bh & (H_ - 1);
    const int b     = bh >> 3;
    const int l     = ltile * ROWS + w;
    const size_t rowbase = ((size_t)bh * L_ + l) * E_;

    // coalesced row loads (64 floats per row: one float2 per lane)
    float2 qv = ((const float2*)(Q  + rowbase))[lane];
    float2 kv = ((const float2*)(Kk + rowbase))[lane];
    float2 vv = ((const float2*)(Vv + rowbase))[lane];
    ((float2*)s_q[w])[lane]      = qv;
    ((float2*)s_q[w])[lane + 32] = qv;   // duplicate
    ((float2*)s_k[w])[lane]      = kv;
    ((float2*)s_v[w])[lane]      = vv;
    __syncwarp();

    // circular correlation: lane computes delays (lane) and (lane+32)
    const float* qd = s_q[w];
    const float* kd = s_k[w];
    float c1 = 0.f, c2 = 0.f;
    #pragma unroll
    for (int e = 0; e < 64; ++e) {
        float kk = kd[e];                      // broadcast
        c1 = fmaf(qd[e + lane],      kk, c1);  // conflict-free (consecutive lanes)
        c2 = fmaf(qd[e + lane + 32], kk, c2);
    }

    s_c[w][lane]      = c1;
    s_c[w][lane + 32] = c2;

    // top-4 over 64 values (2 per lane), jax.lax.top_k tie rule: lower index wins
    float a1 = c1, a2 = c2;
    float wv[4]; int wd[4];
    #pragma unroll
    for (int i = 0; i < 4; ++i) {
        float bv; int bi;
        if (a1 >= a2) { bv = a1; bi = lane; } else { bv = a2; bi = lane + 32; }
        #pragma unroll
        for (int off = 16; off; off >>= 1) {
            float ov = __shfl_xor_sync(0xffffffffu, bv, off);
            int   oi = __shfl_xor_sync(0xffffffffu, bi, off);
            if (ov > bv || (ov == bv && oi < bi)) { bv = ov; bi = oi; }
        }
        wv[i] = bv; wd[i] = bi;                // identical on all lanes
        if (bi == lane)      a1 = -CUDART_INF_F;
        if (bi == lane + 32) a2 = -CUDART_INF_F;
    }

    // softmax over the 4 weights (wv[0] is the max)
    float p[4]; float z = 0.f;
    #pragma unroll
    for (int i = 0; i < 4; ++i) { p[i] = __expf(wv[i] - wv[0]); z += p[i]; }
    const float rz = 1.f / z;

    // delay aggregation
    const float* vd = s_v[w];
    float o1 = 0.f, o2 = 0.f;
    #pragma unroll
    for (int i = 0; i < 4; ++i) {
        float pi = p[i] * rz;
        o1 = fmaf(pi, vd[(lane + wd[i]) & 63],      o1);
        o2 = fmaf(pi, vd[(lane + 32 + wd[i]) & 63], o2);
    }
    outV[rowbase + lane]      = o1;
    outV[rowbase + lane + 32] = o2;

    // block-wide coalesced transposed corr write: outC[((b*E+e)*H+h)*L + l0 + r]
    __syncthreads();
    const int l0 = ltile * ROWS;
    #pragma unroll
    for (int idx = threadIdx.x; idx < E_ * ROWS; idx += NTHREADS) {
        int e = idx >> 5;          // ROWS == 32
        int r = idx & 31;
        outC[(((size_t)b * E_ + e) * H_ + h) * L_ + l0 + r] = s_c[r][e];
    }
}

extern "C" void kernel_launch(void* const* d_in, const int* in_sizes, int n_in,
                              void* d_out, int out_size)
{
    const float* Q = (const float*)d_in[0];
    const float* K = (const float*)d_in[1];
    const float* V = (const float*)d_in[2];
    float* outV = (float*)d_out;
    float* outC = outV + (size_t)B_ * H_ * L_ * E_;

    dim3 grid(L_ / ROWS, B_ * H_);
    ac_kernel<<<grid, NTHREADS>>>(Q, K, V, outV, outC);
}

// round 2
// speedup vs baseline: 2.0288x; 2.0288x over previous
#include <cuda_runtime.h>
#include <math_constants.h>

#define B_ 32
#define H_ 8
#define L_ 2048
#define E_ 64

#define NTHREADS 256
#define ROWS 32          // rows (l positions) per block
#define RP   16          // row-pairs per block

// packed f32x2 fma: d = a*b + d (elementwise on packed float2 in a 64-bit reg)
__device__ __forceinline__ void ffma2(unsigned long long& d,
                                      unsigned long long a,
                                      unsigned long long b) {
    asm("fma.rn.f32x2 %0, %1, %2, %0;" : "+l"(d) : "l"(a), "l"(b));
}

// AutoCorrelation (Autoformer):
//   corr[b,h,l,d] = sum_e q[b,h,l,(e+d)%64] * k[b,h,l,e]
//   top-4 over d, softmax, V_out[e] = sum_i p_i * v[(e+d_i)%64]
//   outputs: V (B,H,L,E) then corr transposed to (B,E,H,L)
__global__ __launch_bounds__(NTHREADS, 4)
void ac_kernel(const float* __restrict__ Q, const float* __restrict__ Kk,
               const float* __restrict__ Vv, float* __restrict__ outV,
               float* __restrict__ outC)
{
    // s_qq: per row-pair, 128 interleaved pairs (q duplicated to avoid wrap),
    //       stored as swizzled 16B chunks: chunk c at position c ^ ((c>>3)&1)
    __shared__ __align__(16) float s_qq[RP][256];
    __shared__ __align__(16) float s_kk[RP][128];   // 64 interleaved pairs
    __shared__ float s_v[ROWS][66];
    __shared__ float s_c[ROWS][67];

    const int t     = threadIdx.x;
    const int ltile = blockIdx.x;
    const int bh    = blockIdx.y;
    const int h     = bh & (H_ - 1);
    const int b     = bh >> 3;
    const int l0    = ltile * ROWS;

    // ---------------- load + interleave (warp loads exactly its own rows) ----
    {
        const int r   = t >> 3;          // block-local row 0..31
        const int g   = t & 7;           // 8 threads per row
        const int rp  = r >> 1;
        const int par = r & 1;
        const size_t rowbase = ((size_t)bh * L_ + l0 + r) * E_;
        const int col = 8 * g;

        float4 q0 = *(const float4*)(Q  + rowbase + col);
        float4 q1 = *(const float4*)(Q  + rowbase + col + 4);
        float4 k0 = *(const float4*)(Kk + rowbase + col);
        float4 k1 = *(const float4*)(Kk + rowbase + col + 4);
        float4 v0 = *(const float4*)(Vv + rowbase + col);
        float4 v1 = *(const float4*)(Vv + rowbase + col + 4);

        float qf[8] = {q0.x,q0.y,q0.z,q0.w,q1.x,q1.y,q1.z,q1.w};
        float kf[8] = {k0.x,k0.y,k0.z,k0.w,k1.x,k1.y,k1.z,k1.w};
        float vf[8] = {v0.x,v0.y,v0.z,v0.w,v1.x,v1.y,v1.z,v1.w};

        #pragma unroll
        for (int u = 0; u < 8; ++u) {
            int i  = col + u;
            // q (original + duplicate at +64), swizzled interleaved
            int c0  = i >> 1;
            int p0  = c0 ^ ((c0 >> 3) & 1);
            s_qq[rp][p0 * 4 + (i & 1) * 2 + par] = qf[u];
            int i2  = i + 64;
            int c2  = i2 >> 1;
            int p2  = c2 ^ ((c2 >> 3) & 1);
            s_qq[rp][p2 * 4 + (i2 & 1) * 2 + par] = qf[u];
            // k interleaved (no swizzle: broadcast reads)
            s_kk[rp][i * 2 + par] = kf[u];
            // v plain
            s_v[r][i] = vf[u];
        }
    }
    __syncwarp();

    // ---------------- correlation: FIR window + f32x2, 2 rows per lane -------
    const int lane = t & 31;
    const int sub  = lane & 15;
    const int half = lane >> 4;
    const int w    = t >> 5;
    const int rp   = 2 * w + half;      // row-pair handled by this half-warp
    const int d0   = 4 * sub;           // this lane's 4 delays: d0..d0+3

    const float* qq = s_qq[rp];
    const float* kk = s_kk[rp];

    #define LDQ(c) (*(const ulonglong2*)(qq + 4 * ((c) ^ (((c) >> 3) & 1))))
    #define LDK(c) (*(const ulonglong2*)(kk + 4 * (c)))

    unsigned long long Wr[8];
    {
        ulonglong2 t0 = LDQ(d0 >> 1);       Wr[0] = t0.x; Wr[1] = t0.y;
        ulonglong2 t1 = LDQ((d0 >> 1) + 1); Wr[2] = t1.x; Wr[3] = t1.y;
    }
    unsigned long long acc[4] = {0ull, 0ull, 0ull, 0ull};

    #pragma unroll
    for (int blk = 0; blk < 16; ++blk) {
        const int e0 = blk * 4;
        const int cb = (e0 + d0) >> 1;
        ulonglong2 t0 = LDQ(cb + 2); Wr[4] = t0.x; Wr[5] = t0.y;
        ulonglong2 t1 = LDQ(cb + 3); Wr[6] = t1.x; Wr[7] = t1.y;
        ulonglong2 ka = LDK(e0 >> 1), kb = LDK((e0 >> 1) + 1);
        unsigned long long kp[4] = {ka.x, ka.y, kb.x, kb.y};
        #pragma unroll
        for (int tt = 0; tt < 4; ++tt)
            #pragma unroll
            for (int j = 0; j < 4; ++j)
                ffma2(acc[j], Wr[tt + j], kp[tt]);
        Wr[0] = Wr[4]; Wr[1] = Wr[5]; Wr[2] = Wr[6]; Wr[3] = Wr[7];
    }

    // unpack + stage corr for the transposed output
    float cx[4], cy[4];
    #pragma unroll
    for (int j = 0; j < 4; ++j) {
        float2 f2 = *reinterpret_cast<float2*>(&acc[j]);
        cx[j] = f2.x; cy[j] = f2.y;
        s_c[2 * rp][d0 + j]     = f2.x;
        s_c[2 * rp + 1][d0 + j] = f2.y;
    }

    // ---------------- top-4 + softmax + delay aggregation (2 passes) --------
    #pragma unroll
    for (int pass = 0; pass < 2; ++pass) {
        const int row = 2 * rp + pass;
        float a0 = pass ? cy[0] : cx[0];
        float a1 = pass ? cy[1] : cx[1];
        float a2 = pass ? cy[2] : cx[2];
        float a3 = pass ? cy[3] : cx[3];

        float wv[4]; int wd[4];
        #pragma unroll
        for (int i = 0; i < 4; ++i) {
            // local argmax, lowest index wins on ties
            float bv = a0; int bj = 0;
            if (a1 > bv) { bv = a1; bj = 1; }
            if (a2 > bv) { bv = a2; bj = 2; }
            if (a3 > bv) { bv = a3; bj = 3; }
            int bi = d0 + bj;
            // 16-lane butterfly (stays within half-warp), lexicographic
            #pragma unroll
            for (int off = 8; off; off >>= 1) {
                float ov = __shfl_xor_sync(0xffffffffu, bv, off);
                int   oi = __shfl_xor_sync(0xffffffffu, bi, off);
                if (ov > bv || (ov == bv && oi < bi)) { bv = ov; bi = oi; }
            }
            wv[i] = bv; wd[i] = bi;
            int loc = bi - d0;               // remove if ours
            if (loc == 0) a0 = -CUDART_INF_F;
            if (loc == 1) a1 = -CUDART_INF_F;
            if (loc == 2) a2 = -CUDART_INF_F;
            if (loc == 3) a3 = -CUDART_INF_F;
        }

        float p[4]; float z = 0.f;
        #pragma unroll
        for (int i = 0; i < 4; ++i) { p[i] = __expf(wv[i] - wv[0]); z += p[i]; }
        const float rz = 1.f / z;

        const float* vd = s_v[row];
        float o0 = 0.f, o1 = 0.f, o2 = 0.f, o3 = 0.f;
        #pragma unroll
        for (int i = 0; i < 4; ++i) {
            float pi = p[i] * rz;
            int base = d0 + wd[i];
            o0 = fmaf(pi, vd[(base + 0) & 63], o0);
            o1 = fmaf(pi, vd[(base + 1) & 63], o1);
            o2 = fmaf(pi, vd[(base + 2) & 63], o2);
            o3 = fmaf(pi, vd[(base + 3) & 63], o3);
        }
        const size_t vbase = ((size_t)bh * L_ + l0 + row) * E_;
        *(float4*)(outV + vbase + d0) = make_float4(o0, o1, o2, o3);
    }

    // ---------------- transposed corr write: outC[b,e,h,l] -------------------
    __syncthreads();
    #pragma unroll
    for (int idx = t; idx < E_ * ROWS; idx += NTHREADS) {
        int e = idx >> 5;            // ROWS == 32
        int r = idx & 31;
        outC[(((size_t)b * E_ + e) * H_ + h) * (size_t)L_ + l0 + r] = s_c[r][e];
    }
}

extern "C" void kernel_launch(void* const* d_in, const int* in_sizes, int n_in,
                              void* d_out, int out_size)
{
    const float* Q = (const float*)d_in[0];
    const float* K = (const float*)d_in[1];
    const float* V = (const float*)d_in[2];
    float* outV = (float*)d_out;
    float* outC = outV + (size_t)B_ * H_ * L_ * E_;

    dim3 grid(L_ / ROWS, B_ * H_);
    ac_kernel<<<grid, NTHREADS>>>(Q, K, V, outV, outC);
}